// round 10
// baseline (speedup 1.0000x reference)
#include <cuda_runtime.h>
#include <cuda_bf16.h>
#include <math_constants.h>
#include <cstdint>
#include <climits>

#define B_N 32768
#define D_N 128
#define K_N 4096
#define CAP 128
#define DELTA_I 2731          // 2.5e-4 * (21 * 520192)
#define NTILES 32
#define KSTEPS 4              // 128 / 32 (k per s8 mma)

// phase-1 smem layout (bytes). int8 rows padded to 144B for conflict-free LDSM.
#define ROWB 144
#define XS_OFF   0
#define E0_OFF   18432
#define E1_OFF   36864
#define SCNT_OFF 55296
#define SM_TOTAL 55808

#define SX 21.0f              // x int8 scale (range +-6.05)
#define SE 520192.0f          // e int8 scale (4096*127)

__device__ uint8_t g_e8[K_N * D_N];
__device__ int2   g_cand[(size_t)B_N * CAP];   // .x = int score, .y = index
__device__ int    g_ccnt[B_N];
__device__ float  g_esq[K_N];
__device__ int    g_counts[K_N];
__device__ double g_sum_e, g_sum_q;

__device__ __forceinline__ uint32_t smem_u32(const void* p) {
    uint32_t a;
    asm("{ .reg .u64 t; cvta.to.shared.u64 t, %1; cvt.u32.u64 %0, t; }"
        : "=r"(a) : "l"(p));
    return a;
}
__device__ __forceinline__ void ldsm_x4(uint32_t& r0, uint32_t& r1,
                                        uint32_t& r2, uint32_t& r3, uint32_t addr) {
    asm volatile("ldmatrix.sync.aligned.m8n8.x4.shared.b16 {%0,%1,%2,%3}, [%4];"
        : "=r"(r0), "=r"(r1), "=r"(r2), "=r"(r3) : "r"(addr));
}
__device__ __forceinline__ void mma16832s8(int* c, uint32_t a0, uint32_t a1,
                                           uint32_t a2, uint32_t a3,
                                           uint32_t b0, uint32_t b1) {
    asm volatile("mma.sync.aligned.m16n8k32.row.col.s32.s8.s8.s32 "
        "{%0,%1,%2,%3}, {%4,%5,%6,%7}, {%8,%9}, {%0,%1,%2,%3};"
        : "+r"(c[0]), "+r"(c[1]), "+r"(c[2]), "+r"(c[3])
        : "r"(a0), "r"(a1), "r"(a2), "r"(a3), "r"(b0), "r"(b1));
}
__device__ __forceinline__ int q8x(float v) {
    int r = __float2int_rn(v * SX);
    return max(-127, min(127, r));
}
__device__ __forceinline__ uint32_t pack4(int a, int b, int c, int d) {
    return (uint32_t)(a & 255) | ((uint32_t)(b & 255) << 8) |
           ((uint32_t)(c & 255) << 16) | ((uint32_t)(d & 255) << 24);
}
#define CP_ASYNC16(dst, src) \
    asm volatile("cp.async.cg.shared.global [%0], [%1], 16;" \
        :: "r"(dst), "l"(src) : "memory")
#define CP_COMMIT() asm volatile("cp.async.commit_group;" ::: "memory")
#define CP_WAIT(n)  asm volatile("cp.async.wait_group %0;" :: "n"(n) : "memory")

// ---------------------------------------------------------------------------
// init: warp per E row — |e|^2 (fp64, shuffle-reduced), int8 convert, zeroing
// ---------------------------------------------------------------------------
__global__ void __launch_bounds__(256) k_init(const float* __restrict__ E) {
    const int warp = threadIdx.x >> 5;
    const int lane = threadIdx.x & 31;
    const int row  = blockIdx.x * 8 + warp;

    float4 v = ((const float4*)(E + (size_t)row * D_N))[lane];
    double s = 0.0;
    s += (double)v.x * (double)v.x;
    s += (double)v.y * (double)v.y;
    s += (double)v.z * (double)v.z;
    s += (double)v.w * (double)v.w;
    #pragma unroll
    for (int off = 16; off > 0; off >>= 1)
        s += __shfl_xor_sync(0xffffffffu, s, off);

    int q0 = max(-127, min(127, __float2int_rn(v.x * SE)));
    int q1 = max(-127, min(127, __float2int_rn(v.y * SE)));
    int q2 = max(-127, min(127, __float2int_rn(v.z * SE)));
    int q3 = max(-127, min(127, __float2int_rn(v.w * SE)));
    ((uint32_t*)g_e8)[(size_t)row * 32 + lane] = pack4(q0, q1, q2, q3);

    if (lane == 0) { g_esq[row] = (float)s; g_counts[row] = 0; }
    if (row == 0 && lane == 0) { g_sum_e = 0.0; g_sum_q = 0.0; }
}

// ---------------------------------------------------------------------------
// phase1: int8 mma.sync GEMM (scaled scores = 21*520192 * X@E^T) with per-half
// register-threshold candidate selection; stores (int score, index) pairs.
// X converted fp32->int8 in the prologue; E tiles via cp.async double-buffer.
// ---------------------------------------------------------------------------
__global__ void __launch_bounds__(256, 2) k_phase1(const float* __restrict__ X) {
    extern __shared__ char smem[];
    int* scnt = (int*)(smem + SCNT_OFF);   // [128]

    const int tid  = threadIdx.x;
    const int lane = tid & 31;
    const int wid  = tid >> 5;
    const int wm   = wid >> 1;          // 0..3  (rows 32*wm .. +32)
    const int wn   = wid & 1;           // 0..1  (cols 64*wn .. +64)
    const int row0 = blockIdx.x * 128;

    if (tid < 128) scnt[tid] = 0;

    const uint32_t sb = smem_u32(smem);

    // issue E tile 0 via cp.async (16KB = 1024 x 16B, 4 per thread)
    #pragma unroll
    for (int i = 0; i < 4; i++) {
        int m = tid + i * 256; int r = m >> 3, c16 = m & 7;
        uint32_t dst = sb + E0_OFF + (uint32_t)(r * ROWB + c16 * 16);
        const char* src = (const char*)g_e8 + (size_t)r * 128 + c16 * 16;
        CP_ASYNC16(dst, src);
    }
    CP_COMMIT();

    // X tile: load fp32, convert to int8 (scale 21), store padded
    #pragma unroll
    for (int i = 0; i < 4; i++) {
        int m = tid + i * 256; int r = m >> 3, c16 = m & 7;
        const float4* xrow = (const float4*)X + (size_t)(row0 + r) * 32 + c16 * 4;
        uint4 o;
        {
            float4 f = xrow[0];
            o.x = pack4(q8x(f.x), q8x(f.y), q8x(f.z), q8x(f.w));
        }
        {
            float4 f = xrow[1];
            o.y = pack4(q8x(f.x), q8x(f.y), q8x(f.z), q8x(f.w));
        }
        {
            float4 f = xrow[2];
            o.z = pack4(q8x(f.x), q8x(f.y), q8x(f.z), q8x(f.w));
        }
        {
            float4 f = xrow[3];
            o.w = pack4(q8x(f.x), q8x(f.y), q8x(f.z), q8x(f.w));
        }
        *(uint4*)(smem + XS_OFF + r * ROWB + c16 * 16) = o;
    }
    __syncthreads();

    // ldmatrix lane bases (identical structure to the bf16 version; byte units)
    const uint32_t pA = sb + XS_OFF + (uint32_t)((wm * 32 + (lane & 15)) * ROWB)
                        + (uint32_t)((lane >> 4) * 16);
    const int n_lane = ((lane >> 4) << 3) + (lane & 7);
    const uint32_t pB_off = (uint32_t)((wn * 64 + n_lane) * ROWB)
                            + (uint32_t)(((lane >> 3) & 1) * 16);

    const int qr = lane >> 2;           // quad row id 0..7
    const int qc = lane & 3;

    // per-half running row maxima (int scores)
    int thrA[2] = { INT_MIN, INT_MIN };
    int thrB[2] = { INT_MIN, INT_MIN };

    for (int t = 0; t < NTILES; t++) {
        const int buf = t & 1;

        // stage tile t+1 into the other buffer, then wait for tile t
        if (t + 1 < NTILES) {
            const int nb = (t + 1) & 1;
            const uint32_t ebase = sb + (nb ? E1_OFF : E0_OFF);
            #pragma unroll
            for (int i = 0; i < 4; i++) {
                int m = tid + i * 256; int r = m >> 3, c16 = m & 7;
                uint32_t dst = ebase + (uint32_t)(r * ROWB + c16 * 16);
                const char* src = (const char*)g_e8
                                  + (size_t)((t + 1) * 128 + r) * 128 + c16 * 16;
                CP_ASYNC16(dst, src);
            }
            CP_COMMIT();
            CP_WAIT(1);
        } else {
            CP_WAIT(0);
        }
        __syncthreads();

        const uint32_t pB = sb + (buf ? E1_OFF : E0_OFF) + pB_off;

        int acc[2][8][4];
        #pragma unroll
        for (int mt = 0; mt < 2; mt++)
            #pragma unroll
            for (int nt = 0; nt < 8; nt++)
                #pragma unroll
                for (int j = 0; j < 4; j++) acc[mt][nt][j] = 0;

        #pragma unroll
        for (int s = 0; s < KSTEPS; s++) {
            uint32_t a[2][4];
            #pragma unroll
            for (int mt = 0; mt < 2; mt++)
                ldsm_x4(a[mt][0], a[mt][1], a[mt][2], a[mt][3],
                        pA + (uint32_t)(mt * 16 * ROWB) + (uint32_t)(s * 32));
            uint32_t b[4][4];
            #pragma unroll
            for (int p = 0; p < 4; p++)
                ldsm_x4(b[p][0], b[p][1], b[p][2], b[p][3],
                        pB + (uint32_t)(p * 16 * ROWB) + (uint32_t)(s * 32));
            #pragma unroll
            for (int mt = 0; mt < 2; mt++)
                #pragma unroll
                for (int nt = 0; nt < 8; nt++) {
                    uint32_t b0 = (nt & 1) ? b[nt >> 1][2] : b[nt >> 1][0];
                    uint32_t b1 = (nt & 1) ? b[nt >> 1][3] : b[nt >> 1][1];
                    mma16832s8(acc[mt][nt], a[mt][0], a[mt][1], a[mt][2], a[mt][3],
                               b0, b1);
                }
        }

        // ---- epilogue: warp-local row maxima, guarded emission (int) ----
        #pragma unroll
        for (int mt = 0; mt < 2; mt++) {
            int ma = INT_MIN, mb = INT_MIN;
            #pragma unroll
            for (int nt = 0; nt < 8; nt++) {
                ma = max(ma, max(acc[mt][nt][0], acc[mt][nt][1]));
                mb = max(mb, max(acc[mt][nt][2], acc[mt][nt][3]));
            }
            ma = max(ma, __shfl_xor_sync(0xffffffffu, ma, 1));
            ma = max(ma, __shfl_xor_sync(0xffffffffu, ma, 2));
            mb = max(mb, __shfl_xor_sync(0xffffffffu, mb, 1));
            mb = max(mb, __shfl_xor_sync(0xffffffffu, mb, 2));
            // (ma + DELTA_I >= thr) form avoids INT_MIN - DELTA underflow
            const bool anyA = (ma + DELTA_I >= thrA[mt]);
            const bool anyB = (mb + DELTA_I >= thrB[mt]);
            thrA[mt] = max(thrA[mt], ma);
            thrB[mt] = max(thrB[mt], mb);
            const int rA = wm * 32 + mt * 16 + qr;
            const int rB = rA + 8;
            if (anyA) {
                const int cutA = thrA[mt] - DELTA_I;
                #pragma unroll
                for (int nt = 0; nt < 8; nt++) {
                    int kb = t * 128 + wn * 64 + nt * 8 + 2 * qc;
                    if (acc[mt][nt][0] >= cutA) {
                        int p = atomicAdd(&scnt[rA], 1);
                        if (p < CAP) g_cand[(size_t)(row0 + rA) * CAP + p] =
                            make_int2(acc[mt][nt][0], kb);
                    }
                    if (acc[mt][nt][1] >= cutA) {
                        int p = atomicAdd(&scnt[rA], 1);
                        if (p < CAP) g_cand[(size_t)(row0 + rA) * CAP + p] =
                            make_int2(acc[mt][nt][1], kb + 1);
                    }
                }
            }
            if (anyB) {
                const int cutB = thrB[mt] - DELTA_I;
                #pragma unroll
                for (int nt = 0; nt < 8; nt++) {
                    int kb = t * 128 + wn * 64 + nt * 8 + 2 * qc;
                    if (acc[mt][nt][2] >= cutB) {
                        int p = atomicAdd(&scnt[rB], 1);
                        if (p < CAP) g_cand[(size_t)(row0 + rB) * CAP + p] =
                            make_int2(acc[mt][nt][2], kb);
                    }
                    if (acc[mt][nt][3] >= cutB) {
                        int p = atomicAdd(&scnt[rB], 1);
                        if (p < CAP) g_cand[(size_t)(row0 + rB) * CAP + p] =
                            make_int2(acc[mt][nt][3], kb + 1);
                    }
                }
            }
        }
        __syncthreads();   // buf(t) reads done before next iteration's cp.async
    }

    if (tid < 128) g_ccnt[row0 + tid] = scnt[tid];
}

// ---------------------------------------------------------------------------
// rescore + gather (fused): global-max prune on stored int scores, exact fp32
// chains (arithmetic identical to R1-R8), then straight-through output, loss
// sums and histogram using the same smem X. 16 lanes/row, 2 rows/warp.
// ---------------------------------------------------------------------------
__global__ void __launch_bounds__(256) k_rescore_gather(
    const float* __restrict__ X, const float* __restrict__ E,
    float* __restrict__ out, int out_size)
{
    __shared__ float xs[16][132];
    __shared__ double swe[8], swq[8];
    const int warp = threadIdx.x >> 5;
    const int lane = threadIdx.x & 31;
    const int grp  = lane >> 4;     // 0..1: row within warp
    const int l16  = lane & 15;     // lane within 16-lane group
    const int rowL = warp * 2 + grp;
    const int row  = blockIdx.x * 16 + rowL;

    for (int i = threadIdx.x; i < 16 * 32; i += 256) {
        int r = i >> 5, c = i & 31;
        float4 v = ((const float4*)X)[(size_t)(blockIdx.x * 16 + r) * 32 + c];
        *(float4*)&xs[r][c * 4] = v;
    }
    __syncthreads();

    const float* xr = xs[rowL];
    // A = |x|^2 in fp64, reduced within the 16-lane group
    double s = 0.0;
    #pragma unroll
    for (int i = 0; i < 8; i++) { double v = (double)xr[l16 * 8 + i]; s += v * v; }
    #pragma unroll
    for (int off = 1; off < 16; off <<= 1)
        s += __shfl_xor_sync(0xffffffffu, s, off);
    float A = (float)s;

    int n = g_ccnt[row];
    float best = CUDART_INF_F;
    int bi = 0x7fffffff;

    if (n <= CAP) {
        const int2* cd = &g_cand[(size_t)row * CAP];
        // pass A: global int-score max over this row's candidates
        int vmax = INT_MIN;
        for (int j = l16; j < n; j += 16)
            vmax = max(vmax, cd[j].x);
        #pragma unroll
        for (int off = 1; off < 16; off <<= 1)
            vmax = max(vmax, __shfl_xor_sync(0xffffffffu, vmax, off));
        const int cut = vmax - DELTA_I;
        // pass B: exact fp32 chain only for survivors
        for (int j = l16; j < n; j += 16) {
            int2 c = cd[j];
            if (c.x < cut) continue;
            int k = c.y;
            const float4* e4 = (const float4*)(E + (size_t)k * D_N);
            float acc = 0.0f;
            #pragma unroll 8
            for (int i = 0; i < 32; i++) {
                float4 xv = *(const float4*)&xr[i * 4];
                float4 ev = e4[i];
                acc = __fmaf_rn(xv.x, ev.x, acc);
                acc = __fmaf_rn(xv.y, ev.y, acc);
                acc = __fmaf_rn(xv.z, ev.z, acc);
                acc = __fmaf_rn(xv.w, ev.w, acc);
            }
            float tsum = __fadd_rn(A, g_esq[k]);
            float v = __fmaf_rn(-2.0f, acc, tsum);
            if (v < best || (v == best && k < bi)) { best = v; bi = k; }
        }
    } else {
        // safety fallback: exact full scan (unreachable in practice)
        for (int k = l16; k < K_N; k += 16) {
            const float4* e4 = (const float4*)(E + (size_t)k * D_N);
            float acc = 0.0f;
            #pragma unroll 8
            for (int i = 0; i < 32; i++) {
                float4 xv = *(const float4*)&xr[i * 4];
                float4 ev = e4[i];
                acc = __fmaf_rn(xv.x, ev.x, acc);
                acc = __fmaf_rn(xv.y, ev.y, acc);
                acc = __fmaf_rn(xv.z, ev.z, acc);
                acc = __fmaf_rn(xv.w, ev.w, acc);
            }
            float tsum = __fadd_rn(A, g_esq[k]);
            float v = __fmaf_rn(-2.0f, acc, tsum);
            if (v < best || (v == best && k < bi)) { best = v; bi = k; }
        }
    }
    // butterfly reduce within 16-lane group -> all lanes hold (best, bi)
    #pragma unroll
    for (int off = 1; off < 16; off <<= 1) {
        float ov = __shfl_xor_sync(0xffffffffu, best, off);
        int   oi = __shfl_xor_sync(0xffffffffu, bi, off);
        if (ov < best || (ov == best && oi < bi)) { best = ov; bi = oi; }
    }

    // ---- gather: straight-through output + loss sums + histogram ----
    const float4* e4 = (const float4*)(E + (size_t)bi * D_N);
    float4 q0 = e4[l16 * 2], q1 = e4[l16 * 2 + 1];
    float4 x0 = *(const float4*)&xr[l16 * 8];
    float4 x1 = *(const float4*)&xr[l16 * 8 + 4];
    float4 o0, o1;
    double se = 0.0, sq = 0.0;
#define VQ_STEP(o, q, x) { \
        float de = __fsub_rn(q, x); float qs = __fadd_rn(x, de); \
        float dq = __fsub_rn(qs, x); \
        o = qs; se += (double)de * (double)de; sq += (double)dq * (double)dq; }
    VQ_STEP(o0.x, q0.x, x0.x)  VQ_STEP(o0.y, q0.y, x0.y)
    VQ_STEP(o0.z, q0.z, x0.z)  VQ_STEP(o0.w, q0.w, x0.w)
    VQ_STEP(o1.x, q1.x, x1.x)  VQ_STEP(o1.y, q1.y, x1.y)
    VQ_STEP(o1.z, q1.z, x1.z)  VQ_STEP(o1.w, q1.w, x1.w)
#undef VQ_STEP
    ((float4*)out)[(size_t)row * 32 + l16 * 2]     = o0;
    ((float4*)out)[(size_t)row * 32 + l16 * 2 + 1] = o1;

    if (l16 == 0) {
        atomicAdd(&g_counts[bi], 1);
        if (out_size >= B_N * D_N + B_N)
            out[(size_t)B_N * D_N + row] = (float)bi;
    }

    // block-reduce loss sums
    #pragma unroll
    for (int off = 16; off > 0; off >>= 1) {
        se += __shfl_down_sync(0xffffffffu, se, off);
        sq += __shfl_down_sync(0xffffffffu, sq, off);
    }
    if (lane == 0) { swe[warp] = se; swq[warp] = sq; }
    __syncthreads();
    if (threadIdx.x == 0) {
        double te = 0.0, tq = 0.0;
        #pragma unroll
        for (int i = 0; i < 8; i++) { te += swe[i]; tq += swq[i]; }
        atomicAdd(&g_sum_e, te);
        atomicAdd(&g_sum_q, tq);
    }
}

// ---------------------------------------------------------------------------
// final: entropy + scalar outputs in one kernel (single CTA)
// ---------------------------------------------------------------------------
__global__ void k_final(float* __restrict__ out, int out_size) {
    if (out_size < B_N * D_N + B_N + 4) return;
    __shared__ double sh[512];
    int tid = threadIdx.x;
    double h = 0.0;
    #pragma unroll
    for (int r = 0; r < K_N / 512; r++) {
        int k = r * 512 + tid;
        float p = __fmul_rn((float)g_counts[k], 1.0f / 32768.0f);
        float t = __fmul_rn(p, logf(__fadd_rn(p, 1e-10f)));
        h += (double)t;
    }
    sh[tid] = h;
    __syncthreads();
    for (int s = 256; s > 0; s >>= 1) {
        if (tid < s) sh[tid] += sh[tid + s];
        __syncthreads();
    }
    if (tid == 0) {
        float H = (float)sh[0];
        float perp = expf(-H);
        double n = (double)B_N * (double)D_N;
        float e = (float)(g_sum_e / n);
        float q = (float)(g_sum_q / n);
        float vq = __fadd_rn(q, __fmul_rn(0.25f, e));
        float* s4 = out + (size_t)B_N * D_N + B_N;
        s4[0] = vq; s4[1] = e; s4[2] = q; s4[3] = perp;
    }
}

// ---------------------------------------------------------------------------
extern "C" void kernel_launch(void* const* d_in, const int* in_sizes, int n_in,
                              void* d_out, int out_size)
{
    const float* X = (const float*)d_in[0];
    const float* E = (const float*)d_in[1];
    if (n_in >= 2 && in_sizes[0] == K_N * D_N && in_sizes[1] == B_N * D_N) {
        X = (const float*)d_in[1];
        E = (const float*)d_in[0];
    }
    float* out = (float*)d_out;

    static bool attr_set = false;
    if (!attr_set) {
        cudaFuncSetAttribute(k_phase1,
                             cudaFuncAttributeMaxDynamicSharedMemorySize,
                             SM_TOTAL);
        attr_set = true;
    }

    k_init<<<K_N / 8, 256>>>(E);
    k_phase1<<<B_N / 128, 256, SM_TOTAL>>>(X);
    k_rescore_gather<<<B_N / 16, 256>>>(X, E, out, out_size);
    k_final<<<1, 512>>>(out, out_size);
}

// round 11
// speedup vs baseline: 1.7928x; 1.7928x over previous
#include <cuda_runtime.h>
#include <cuda_bf16.h>
#include <math_constants.h>
#include <cstdint>

#define B_N 32768
#define D_N 128
#define K_N 4096
#define CAP 128
#define DELTA_C 2.5e-4f
#define NTILES 32

// phase-1 smem layout (bytes). Rows padded to 272B (136 bf16) for conflict-free LDSM.
#define ROWB 272
#define XS_OFF   0
#define E0_OFF   34816
#define E1_OFF   69632
#define SCNT_OFF 104448
#define SM_TOTAL 104960

__device__ __nv_bfloat16 g_eb[K_N * D_N];
__device__ int2   g_cand[(size_t)B_N * CAP];   // .x = bf16-GEMM score bits, .y = index
__device__ int    g_ccnt[B_N];
__device__ float  g_esq[K_N];
__device__ int    g_counts[K_N];
__device__ double g_sum_e, g_sum_q;

__device__ __forceinline__ uint32_t smem_u32(const void* p) {
    uint32_t a;
    asm("{ .reg .u64 t; cvta.to.shared.u64 t, %1; cvt.u32.u64 %0, t; }"
        : "=r"(a) : "l"(p));
    return a;
}
__device__ __forceinline__ void ldsm_x4(uint32_t& r0, uint32_t& r1,
                                        uint32_t& r2, uint32_t& r3, uint32_t addr) {
    asm volatile("ldmatrix.sync.aligned.m8n8.x4.shared.b16 {%0,%1,%2,%3}, [%4];"
        : "=r"(r0), "=r"(r1), "=r"(r2), "=r"(r3) : "r"(addr));
}
__device__ __forceinline__ void mma16816(float* c, uint32_t a0, uint32_t a1,
                                         uint32_t a2, uint32_t a3,
                                         uint32_t b0, uint32_t b1) {
    asm volatile("mma.sync.aligned.m16n8k16.row.col.f32.bf16.bf16.f32 "
        "{%0,%1,%2,%3}, {%4,%5,%6,%7}, {%8,%9}, {%0,%1,%2,%3};"
        : "+f"(c[0]), "+f"(c[1]), "+f"(c[2]), "+f"(c[3])
        : "r"(a0), "r"(a1), "r"(a2), "r"(a3), "r"(b0), "r"(b1));
}
__device__ __forceinline__ uint32_t packbf(float a, float b) {
    return ((uint32_t)__bfloat16_as_ushort(__float2bfloat16_rn(b)) << 16) |
            (uint32_t)__bfloat16_as_ushort(__float2bfloat16_rn(a));
}
#define CP_ASYNC16(dst, src) \
    asm volatile("cp.async.cg.shared.global [%0], [%1], 16;" \
        :: "r"(dst), "l"(src) : "memory")
#define CP_COMMIT() asm volatile("cp.async.commit_group;" ::: "memory")
#define CP_WAIT(n)  asm volatile("cp.async.wait_group %0;" :: "n"(n) : "memory")

// ---------------------------------------------------------------------------
// init: warp per E row — |e|^2 (fp64, shuffle-reduced), bf16 convert, zeroing
// ---------------------------------------------------------------------------
__global__ void __launch_bounds__(256) k_init(const float* __restrict__ E) {
    const int warp = threadIdx.x >> 5;
    const int lane = threadIdx.x & 31;
    const int row  = blockIdx.x * 8 + warp;

    float4 v = ((const float4*)(E + (size_t)row * D_N))[lane];
    double s = 0.0;
    s += (double)v.x * (double)v.x;
    s += (double)v.y * (double)v.y;
    s += (double)v.z * (double)v.z;
    s += (double)v.w * (double)v.w;
    #pragma unroll
    for (int off = 16; off > 0; off >>= 1)
        s += __shfl_xor_sync(0xffffffffu, s, off);

    uint2 o;
    o.x = packbf(v.x, v.y);
    o.y = packbf(v.z, v.w);
    ((uint2*)g_eb)[(size_t)row * 32 + lane] = o;

    if (lane == 0) { g_esq[row] = (float)s; g_counts[row] = 0; }
    if (row == 0 && lane == 0) { g_sum_e = 0.0; g_sum_q = 0.0; }
}

// ---------------------------------------------------------------------------
// phase1: bf16 mma.sync GEMM C = X_b @ E_b^T. A (X) fragments hoisted into
// registers for the whole K loop; each 128-col tile processed in two 32-col
// halves so accumulators fit the (256,2) register budget. Per-32-col running
// prefix-max thresholds; stores (score,index) pairs. cp.async double-buffer.
// ---------------------------------------------------------------------------
__global__ void __launch_bounds__(256, 2) k_phase1(const float* __restrict__ X) {
    extern __shared__ char smem[];
    int* scnt = (int*)(smem + SCNT_OFF);   // [128]

    const int tid  = threadIdx.x;
    const int lane = tid & 31;
    const int wid  = tid >> 5;
    const int wm   = wid >> 1;          // 0..3  (rows 32*wm .. +32)
    const int wn   = wid & 1;           // 0..1  (cols 64*wn .. +64)
    const int row0 = blockIdx.x * 128;

    if (tid < 128) scnt[tid] = 0;

    const uint32_t sb = smem_u32(smem);

    // issue E tile 0 via cp.async (group 0)
    #pragma unroll
    for (int i = 0; i < 8; i++) {
        int m = tid + i * 256; int r = m >> 4, c16 = m & 15;
        uint32_t dst = sb + E0_OFF + (uint32_t)(r * ROWB + c16 * 16);
        const char* src = (const char*)g_eb + (size_t)r * 256 + c16 * 16;
        CP_ASYNC16(dst, src);
    }
    CP_COMMIT();

    // X tile: load fp32, convert to bf16, store padded (overlaps with cp.async)
    #pragma unroll
    for (int i = 0; i < 8; i++) {
        int m = tid + i * 256; int r = m >> 4, c16 = m & 15;
        float4 f0 = ((const float4*)X)[(size_t)(row0 + r) * 32 + c16 * 2];
        float4 f1 = ((const float4*)X)[(size_t)(row0 + r) * 32 + c16 * 2 + 1];
        uint4 o;
        o.x = packbf(f0.x, f0.y);
        o.y = packbf(f0.z, f0.w);
        o.z = packbf(f1.x, f1.y);
        o.w = packbf(f1.z, f1.w);
        *(uint4*)(smem + XS_OFF + r * ROWB + c16 * 16) = o;
    }
    __syncthreads();

    const uint32_t pA = sb + XS_OFF + (uint32_t)((wm * 32 + (lane & 15)) * ROWB)
                        + (uint32_t)((lane >> 4) * 8 * 2);
    const int n_lane = ((lane >> 4) << 3) + (lane & 7);
    const uint32_t pB_off = (uint32_t)((wn * 64 + n_lane) * ROWB)
                            + (uint32_t)(((lane >> 3) & 1) * 8 * 2);

    // hoist A fragments for ALL 8 k-steps (invariant across tiles): 64 regs
    uint32_t afr[2][8][4];
    #pragma unroll
    for (int mt = 0; mt < 2; mt++)
        #pragma unroll
        for (int s = 0; s < 8; s++)
            ldsm_x4(afr[mt][s][0], afr[mt][s][1], afr[mt][s][2], afr[mt][s][3],
                    pA + (uint32_t)(mt * 16 * ROWB) + (uint32_t)(s * 32));

    const int qr = lane >> 2;           // quad row id 0..7
    const int qc = lane & 3;

    // running row maxima per (m-tile, row-set); updated per 32-col half-stream
    float thrA[2] = { -CUDART_INF_F, -CUDART_INF_F };
    float thrB[2] = { -CUDART_INF_F, -CUDART_INF_F };

    for (int t = 0; t < NTILES; t++) {
        const int buf = t & 1;

        // stage tile t+1 into the other buffer, then wait for tile t
        if (t + 1 < NTILES) {
            const int nb = (t + 1) & 1;
            const uint32_t ebase = sb + (nb ? E1_OFF : E0_OFF);
            #pragma unroll
            for (int i = 0; i < 8; i++) {
                int m = tid + i * 256; int r = m >> 4, c16 = m & 15;
                uint32_t dst = ebase + (uint32_t)(r * ROWB + c16 * 16);
                const char* src = (const char*)g_eb
                                  + (size_t)((t + 1) * 128 + r) * 256 + c16 * 16;
                CP_ASYNC16(dst, src);
            }
            CP_COMMIT();
            CP_WAIT(1);
        } else {
            CP_WAIT(0);
        }
        __syncthreads();

        const uint32_t pB = sb + (buf ? E1_OFF : E0_OFF) + pB_off;

        // two sequential 32-col halves: acc stays at 32 regs
        #pragma unroll
        for (int h = 0; h < 2; h++) {
            float acc[2][4][4];
            #pragma unroll
            for (int mt = 0; mt < 2; mt++)
                #pragma unroll
                for (int nt = 0; nt < 4; nt++)
                    #pragma unroll
                    for (int j = 0; j < 4; j++) acc[mt][nt][j] = 0.0f;

            #pragma unroll
            for (int s = 0; s < 8; s++) {
                uint32_t b[2][4];
                #pragma unroll
                for (int p = 0; p < 2; p++)
                    ldsm_x4(b[p][0], b[p][1], b[p][2], b[p][3],
                            pB + (uint32_t)((2 * h + p) * 16 * ROWB)
                               + (uint32_t)(s * 32));
                #pragma unroll
                for (int mt = 0; mt < 2; mt++)
                    #pragma unroll
                    for (int nt = 0; nt < 4; nt++) {
                        uint32_t b0 = (nt & 1) ? b[nt >> 1][2] : b[nt >> 1][0];
                        uint32_t b1 = (nt & 1) ? b[nt >> 1][3] : b[nt >> 1][1];
                        mma16816(acc[mt][nt],
                                 afr[mt][s][0], afr[mt][s][1],
                                 afr[mt][s][2], afr[mt][s][3], b0, b1);
                    }
            }

            // ---- epilogue for this half: maxima, guarded emission ----
            #pragma unroll
            for (int mt = 0; mt < 2; mt++) {
                float ma = -CUDART_INF_F, mb = -CUDART_INF_F;
                #pragma unroll
                for (int nt = 0; nt < 4; nt++) {
                    ma = fmaxf(ma, fmaxf(acc[mt][nt][0], acc[mt][nt][1]));
                    mb = fmaxf(mb, fmaxf(acc[mt][nt][2], acc[mt][nt][3]));
                }
                ma = fmaxf(ma, __shfl_xor_sync(0xffffffffu, ma, 1));
                ma = fmaxf(ma, __shfl_xor_sync(0xffffffffu, ma, 2));
                mb = fmaxf(mb, __shfl_xor_sync(0xffffffffu, mb, 1));
                mb = fmaxf(mb, __shfl_xor_sync(0xffffffffu, mb, 2));
                const bool anyA = (ma >= thrA[mt] - DELTA_C);
                const bool anyB = (mb >= thrB[mt] - DELTA_C);
                thrA[mt] = fmaxf(thrA[mt], ma);
                thrB[mt] = fmaxf(thrB[mt], mb);
                const int rA = wm * 32 + mt * 16 + qr;
                const int rB = rA + 8;
                if (anyA) {
                    const float cutA = thrA[mt] - DELTA_C;
                    #pragma unroll
                    for (int nt = 0; nt < 4; nt++) {
                        int kb = t * 128 + wn * 64 + h * 32 + nt * 8 + 2 * qc;
                        if (acc[mt][nt][0] >= cutA) {
                            int p = atomicAdd(&scnt[rA], 1);
                            if (p < CAP) g_cand[(size_t)(row0 + rA) * CAP + p] =
                                make_int2(__float_as_int(acc[mt][nt][0]), kb);
                        }
                        if (acc[mt][nt][1] >= cutA) {
                            int p = atomicAdd(&scnt[rA], 1);
                            if (p < CAP) g_cand[(size_t)(row0 + rA) * CAP + p] =
                                make_int2(__float_as_int(acc[mt][nt][1]), kb + 1);
                        }
                    }
                }
                if (anyB) {
                    const float cutB = thrB[mt] - DELTA_C;
                    #pragma unroll
                    for (int nt = 0; nt < 4; nt++) {
                        int kb = t * 128 + wn * 64 + h * 32 + nt * 8 + 2 * qc;
                        if (acc[mt][nt][2] >= cutB) {
                            int p = atomicAdd(&scnt[rB], 1);
                            if (p < CAP) g_cand[(size_t)(row0 + rB) * CAP + p] =
                                make_int2(__float_as_int(acc[mt][nt][2]), kb);
                        }
                        if (acc[mt][nt][3] >= cutB) {
                            int p = atomicAdd(&scnt[rB], 1);
                            if (p < CAP) g_cand[(size_t)(row0 + rB) * CAP + p] =
                                make_int2(__float_as_int(acc[mt][nt][3]), kb + 1);
                        }
                    }
                }
            }
        }
        __syncthreads();   // buf(t) reads done before next iteration's cp.async
    }

    if (tid < 128) g_ccnt[row0 + tid] = scnt[tid];
}

// ---------------------------------------------------------------------------
// rescore + gather (fused): global-max prune on stored bf16 scores, exact fp32
// chains (arithmetic identical to R1-R8), then straight-through output, loss
// sums and histogram using the same smem X. 16 lanes/row, 2 rows/warp.
// ---------------------------------------------------------------------------
__global__ void __launch_bounds__(256) k_rescore_gather(
    const float* __restrict__ X, const float* __restrict__ E,
    float* __restrict__ out, int out_size)
{
    __shared__ float xs[16][132];
    __shared__ double swe[8], swq[8];
    const int warp = threadIdx.x >> 5;
    const int lane = threadIdx.x & 31;
    const int grp  = lane >> 4;     // 0..1: row within warp
    const int l16  = lane & 15;     // lane within 16-lane group
    const int rowL = warp * 2 + grp;
    const int row  = blockIdx.x * 16 + rowL;

    for (int i = threadIdx.x; i < 16 * 32; i += 256) {
        int r = i >> 5, c = i & 31;
        float4 v = ((const float4*)X)[(size_t)(blockIdx.x * 16 + r) * 32 + c];
        *(float4*)&xs[r][c * 4] = v;
    }
    __syncthreads();

    const float* xr = xs[rowL];
    // A = |x|^2 in fp64, reduced within the 16-lane group
    double s = 0.0;
    #pragma unroll
    for (int i = 0; i < 8; i++) { double v = (double)xr[l16 * 8 + i]; s += v * v; }
    #pragma unroll
    for (int off = 1; off < 16; off <<= 1)
        s += __shfl_xor_sync(0xffffffffu, s, off);
    float A = (float)s;

    int n = g_ccnt[row];
    float best = CUDART_INF_F;
    int bi = 0x7fffffff;

    if (n <= CAP) {
        const int2* cd = &g_cand[(size_t)row * CAP];
        // pass A: global bf16-score max over this row's candidates
        float vmax = -CUDART_INF_F;
        for (int j = l16; j < n; j += 16)
            vmax = fmaxf(vmax, __int_as_float(cd[j].x));
        #pragma unroll
        for (int off = 1; off < 16; off <<= 1)
            vmax = fmaxf(vmax, __shfl_xor_sync(0xffffffffu, vmax, off));
        const float cut = vmax - DELTA_C;
        // pass B: exact fp32 chain only for survivors
        for (int j = l16; j < n; j += 16) {
            int2 c = cd[j];
            if (__int_as_float(c.x) < cut) continue;
            int k = c.y;
            const float4* e4 = (const float4*)(E + (size_t)k * D_N);
            float acc = 0.0f;
            #pragma unroll 8
            for (int i = 0; i < 32; i++) {
                float4 xv = *(const float4*)&xr[i * 4];
                float4 ev = e4[i];
                acc = __fmaf_rn(xv.x, ev.x, acc);
                acc = __fmaf_rn(xv.y, ev.y, acc);
                acc = __fmaf_rn(xv.z, ev.z, acc);
                acc = __fmaf_rn(xv.w, ev.w, acc);
            }
            float tsum = __fadd_rn(A, g_esq[k]);
            float v = __fmaf_rn(-2.0f, acc, tsum);
            if (v < best || (v == best && k < bi)) { best = v; bi = k; }
        }
    } else {
        // safety fallback: exact full scan (unreachable in practice)
        for (int k = l16; k < K_N; k += 16) {
            const float4* e4 = (const float4*)(E + (size_t)k * D_N);
            float acc = 0.0f;
            #pragma unroll 8
            for (int i = 0; i < 32; i++) {
                float4 xv = *(const float4*)&xr[i * 4];
                float4 ev = e4[i];
                acc = __fmaf_rn(xv.x, ev.x, acc);
                acc = __fmaf_rn(xv.y, ev.y, acc);
                acc = __fmaf_rn(xv.z, ev.z, acc);
                acc = __fmaf_rn(xv.w, ev.w, acc);
            }
            float tsum = __fadd_rn(A, g_esq[k]);
            float v = __fmaf_rn(-2.0f, acc, tsum);
            if (v < best || (v == best && k < bi)) { best = v; bi = k; }
        }
    }
    // butterfly reduce within 16-lane group -> all lanes hold (best, bi)
    #pragma unroll
    for (int off = 1; off < 16; off <<= 1) {
        float ov = __shfl_xor_sync(0xffffffffu, best, off);
        int   oi = __shfl_xor_sync(0xffffffffu, bi, off);
        if (ov < best || (ov == best && oi < bi)) { best = ov; bi = oi; }
    }

    // ---- gather: straight-through output + loss sums + histogram ----
    const float4* e4 = (const float4*)(E + (size_t)bi * D_N);
    float4 q0 = e4[l16 * 2], q1 = e4[l16 * 2 + 1];
    float4 x0 = *(const float4*)&xr[l16 * 8];
    float4 x1 = *(const float4*)&xr[l16 * 8 + 4];
    float4 o0, o1;
    double se = 0.0, sq = 0.0;
#define VQ_STEP(o, q, x) { \
        float de = __fsub_rn(q, x); float qs = __fadd_rn(x, de); \
        float dq = __fsub_rn(qs, x); \
        o = qs; se += (double)de * (double)de; sq += (double)dq * (double)dq; }
    VQ_STEP(o0.x, q0.x, x0.x)  VQ_STEP(o0.y, q0.y, x0.y)
    VQ_STEP(o0.z, q0.z, x0.z)  VQ_STEP(o0.w, q0.w, x0.w)
    VQ_STEP(o1.x, q1.x, x1.x)  VQ_STEP(o1.y, q1.y, x1.y)
    VQ_STEP(o1.z, q1.z, x1.z)  VQ_STEP(o1.w, q1.w, x1.w)
#undef VQ_STEP
    ((float4*)out)[(size_t)row * 32 + l16 * 2]     = o0;
    ((float4*)out)[(size_t)row * 32 + l16 * 2 + 1] = o1;

    if (l16 == 0) {
        atomicAdd(&g_counts[bi], 1);
        if (out_size >= B_N * D_N + B_N)
            out[(size_t)B_N * D_N + row] = (float)bi;
    }

    // block-reduce loss sums
    #pragma unroll
    for (int off = 16; off > 0; off >>= 1) {
        se += __shfl_down_sync(0xffffffffu, se, off);
        sq += __shfl_down_sync(0xffffffffu, sq, off);
    }
    if (lane == 0) { swe[warp] = se; swq[warp] = sq; }
    __syncthreads();
    if (threadIdx.x == 0) {
        double te = 0.0, tq = 0.0;
        #pragma unroll
        for (int i = 0; i < 8; i++) { te += swe[i]; tq += swq[i]; }
        atomicAdd(&g_sum_e, te);
        atomicAdd(&g_sum_q, tq);
    }
}

// ---------------------------------------------------------------------------
// final: entropy + scalar outputs in one kernel (single CTA)
// ---------------------------------------------------------------------------
__global__ void k_final(float* __restrict__ out, int out_size) {
    if (out_size < B_N * D_N + B_N + 4) return;
    __shared__ double sh[512];
    int tid = threadIdx.x;
    double h = 0.0;
    #pragma unroll
    for (int r = 0; r < K_N / 512; r++) {
        int k = r * 512 + tid;
        float p = __fmul_rn((float)g_counts[k], 1.0f / 32768.0f);
        float t = __fmul_rn(p, logf(__fadd_rn(p, 1e-10f)));
        h += (double)t;
    }
    sh[tid] = h;
    __syncthreads();
    for (int s = 256; s > 0; s >>= 1) {
        if (tid < s) sh[tid] += sh[tid + s];
        __syncthreads();
    }
    if (tid == 0) {
        float H = (float)sh[0];
        float perp = expf(-H);
        double n = (double)B_N * (double)D_N;
        float e = (float)(g_sum_e / n);
        float q = (float)(g_sum_q / n);
        float vq = __fadd_rn(q, __fmul_rn(0.25f, e));
        float* s4 = out + (size_t)B_N * D_N + B_N;
        s4[0] = vq; s4[1] = e; s4[2] = q; s4[3] = perp;
    }
}

// ---------------------------------------------------------------------------
extern "C" void kernel_launch(void* const* d_in, const int* in_sizes, int n_in,
                              void* d_out, int out_size)
{
    const float* X = (const float*)d_in[0];
    const float* E = (const float*)d_in[1];
    if (n_in >= 2 && in_sizes[0] == K_N * D_N && in_sizes[1] == B_N * D_N) {
        X = (const float*)d_in[1];
        E = (const float*)d_in[0];
    }
    float* out = (float*)d_out;

    static bool attr_set = false;
    if (!attr_set) {
        cudaFuncSetAttribute(k_phase1,
                             cudaFuncAttributeMaxDynamicSharedMemorySize,
                             SM_TOTAL);
        attr_set = true;
    }

    k_init<<<K_N / 8, 256>>>(E);
    k_phase1<<<B_N / 128, 256, SM_TOTAL>>>(X);
    k_rescore_gather<<<B_N / 16, 256>>>(X, E, out, out_size);
    k_final<<<1, 512>>>(out, out_size);
}

// round 12
// speedup vs baseline: 1.8171x; 1.0136x over previous
#include <cuda_runtime.h>
#include <cuda_bf16.h>
#include <math_constants.h>
#include <cstdint>

#define B_N 32768
#define D_N 128
#define K_N 4096
#define CAP 128
#define DELTA_C 2.5e-4f
#define NTILES 32

// phase-1 smem layout (bytes). Rows padded to 272B (136 bf16) for conflict-free LDSM.
#define ROWB 272
#define XS_OFF   0
#define E0_OFF   34816
#define E1_OFF   69632
#define SCNT_OFF 104448
#define SM_TOTAL 104960

__device__ __nv_bfloat16 g_eb[K_N * D_N];
__device__ int2   g_cand[(size_t)B_N * CAP];   // .x = bf16-GEMM score bits, .y = index
__device__ int    g_ccnt[B_N];
__device__ float  g_esq[K_N];
__device__ int    g_counts[K_N];
__device__ double g_sum_e, g_sum_q;

__device__ __forceinline__ uint32_t smem_u32(const void* p) {
    uint32_t a;
    asm("{ .reg .u64 t; cvta.to.shared.u64 t, %1; cvt.u32.u64 %0, t; }"
        : "=r"(a) : "l"(p));
    return a;
}
__device__ __forceinline__ void ldsm_x4(uint32_t& r0, uint32_t& r1,
                                        uint32_t& r2, uint32_t& r3, uint32_t addr) {
    asm volatile("ldmatrix.sync.aligned.m8n8.x4.shared.b16 {%0,%1,%2,%3}, [%4];"
        : "=r"(r0), "=r"(r1), "=r"(r2), "=r"(r3) : "r"(addr));
}
__device__ __forceinline__ void mma16816(float* c, uint32_t a0, uint32_t a1,
                                         uint32_t a2, uint32_t a3,
                                         uint32_t b0, uint32_t b1) {
    asm volatile("mma.sync.aligned.m16n8k16.row.col.f32.bf16.bf16.f32 "
        "{%0,%1,%2,%3}, {%4,%5,%6,%7}, {%8,%9}, {%0,%1,%2,%3};"
        : "+f"(c[0]), "+f"(c[1]), "+f"(c[2]), "+f"(c[3])
        : "r"(a0), "r"(a1), "r"(a2), "r"(a3), "r"(b0), "r"(b1));
}
__device__ __forceinline__ uint32_t packbf(float a, float b) {
    return ((uint32_t)__bfloat16_as_ushort(__float2bfloat16_rn(b)) << 16) |
            (uint32_t)__bfloat16_as_ushort(__float2bfloat16_rn(a));
}
#define CP_ASYNC16(dst, src) \
    asm volatile("cp.async.cg.shared.global [%0], [%1], 16;" \
        :: "r"(dst), "l"(src) : "memory")
#define CP_COMMIT() asm volatile("cp.async.commit_group;" ::: "memory")
#define CP_WAIT(n)  asm volatile("cp.async.wait_group %0;" :: "n"(n) : "memory")

// ---------------------------------------------------------------------------
// init: warp per E row — |e|^2 (fp64, shuffle-reduced), bf16 convert, zeroing
// ---------------------------------------------------------------------------
__global__ void __launch_bounds__(256) k_init(const float* __restrict__ E) {
    const int warp = threadIdx.x >> 5;
    const int lane = threadIdx.x & 31;
    const int row  = blockIdx.x * 8 + warp;

    float4 v = ((const float4*)(E + (size_t)row * D_N))[lane];
    double s = 0.0;
    s += (double)v.x * (double)v.x;
    s += (double)v.y * (double)v.y;
    s += (double)v.z * (double)v.z;
    s += (double)v.w * (double)v.w;
    #pragma unroll
    for (int off = 16; off > 0; off >>= 1)
        s += __shfl_xor_sync(0xffffffffu, s, off);

    uint2 o;
    o.x = packbf(v.x, v.y);
    o.y = packbf(v.z, v.w);
    ((uint2*)g_eb)[(size_t)row * 32 + lane] = o;

    if (lane == 0) { g_esq[row] = (float)s; g_counts[row] = 0; }
    if (row == 0 && lane == 0) { g_sum_e = 0.0; g_sum_q = 0.0; }
}

// ---------------------------------------------------------------------------
// phase1: bf16 mma.sync GEMM C = X_b @ E_b^T with per-half register-threshold
// candidate selection (stores (score,index) pairs). X converted fp32->bf16 in
// the prologue; E tiles staged via cp.async double-buffering.
// (byte-identical to the R8 kernel that measured 217.3us)
// ---------------------------------------------------------------------------
__global__ void __launch_bounds__(256, 2) k_phase1(const float* __restrict__ X) {
    extern __shared__ char smem[];
    int* scnt = (int*)(smem + SCNT_OFF);   // [128]

    const int tid  = threadIdx.x;
    const int lane = tid & 31;
    const int wid  = tid >> 5;
    const int wm   = wid >> 1;          // 0..3  (rows 32*wm .. +32)
    const int wn   = wid & 1;           // 0..1  (cols 64*wn .. +64)
    const int row0 = blockIdx.x * 128;

    if (tid < 128) scnt[tid] = 0;

    const uint32_t sb = smem_u32(smem);

    // issue E tile 0 via cp.async (group 0)
    #pragma unroll
    for (int i = 0; i < 8; i++) {
        int m = tid + i * 256; int r = m >> 4, c16 = m & 15;
        uint32_t dst = sb + E0_OFF + (uint32_t)(r * ROWB + c16 * 16);
        const char* src = (const char*)g_eb + (size_t)r * 256 + c16 * 16;
        CP_ASYNC16(dst, src);
    }
    CP_COMMIT();

    // X tile: load fp32, convert to bf16, store padded (overlaps with cp.async)
    #pragma unroll
    for (int i = 0; i < 8; i++) {
        int m = tid + i * 256; int r = m >> 4, c16 = m & 15;
        float4 f0 = ((const float4*)X)[(size_t)(row0 + r) * 32 + c16 * 2];
        float4 f1 = ((const float4*)X)[(size_t)(row0 + r) * 32 + c16 * 2 + 1];
        uint4 o;
        o.x = packbf(f0.x, f0.y);
        o.y = packbf(f0.z, f0.w);
        o.z = packbf(f1.x, f1.y);
        o.w = packbf(f1.z, f1.w);
        *(uint4*)(smem + XS_OFF + r * ROWB + c16 * 16) = o;
    }
    __syncthreads();

    const uint32_t pA = sb + XS_OFF + (uint32_t)((wm * 32 + (lane & 15)) * ROWB)
                        + (uint32_t)((lane >> 4) * 8 * 2);
    const int n_lane = ((lane >> 4) << 3) + (lane & 7);
    const uint32_t pB_off = (uint32_t)((wn * 64 + n_lane) * ROWB)
                            + (uint32_t)(((lane >> 3) & 1) * 8 * 2);

    const int qr = lane >> 2;           // quad row id 0..7
    const int qc = lane & 3;

    // per-half running row maxima (registers)
    float thrA[2] = { -CUDART_INF_F, -CUDART_INF_F };
    float thrB[2] = { -CUDART_INF_F, -CUDART_INF_F };

    for (int t = 0; t < NTILES; t++) {
        const int buf = t & 1;

        // stage tile t+1 into the other buffer, then wait for tile t
        if (t + 1 < NTILES) {
            const int nb = (t + 1) & 1;
            const uint32_t ebase = sb + (nb ? E1_OFF : E0_OFF);
            #pragma unroll
            for (int i = 0; i < 8; i++) {
                int m = tid + i * 256; int r = m >> 4, c16 = m & 15;
                uint32_t dst = ebase + (uint32_t)(r * ROWB + c16 * 16);
                const char* src = (const char*)g_eb
                                  + (size_t)((t + 1) * 128 + r) * 256 + c16 * 16;
                CP_ASYNC16(dst, src);
            }
            CP_COMMIT();
            CP_WAIT(1);
        } else {
            CP_WAIT(0);
        }
        __syncthreads();

        const uint32_t pB = sb + (buf ? E1_OFF : E0_OFF) + pB_off;

        float acc[2][8][4];
        #pragma unroll
        for (int mt = 0; mt < 2; mt++)
            #pragma unroll
            for (int nt = 0; nt < 8; nt++)
                #pragma unroll
                for (int j = 0; j < 4; j++) acc[mt][nt][j] = 0.0f;

        #pragma unroll
        for (int s = 0; s < 8; s++) {
            uint32_t a[2][4];
            #pragma unroll
            for (int mt = 0; mt < 2; mt++)
                ldsm_x4(a[mt][0], a[mt][1], a[mt][2], a[mt][3],
                        pA + (uint32_t)(mt * 16 * ROWB) + (uint32_t)(s * 32));
            uint32_t b[4][4];
            #pragma unroll
            for (int p = 0; p < 4; p++)
                ldsm_x4(b[p][0], b[p][1], b[p][2], b[p][3],
                        pB + (uint32_t)(p * 16 * ROWB) + (uint32_t)(s * 32));
            #pragma unroll
            for (int mt = 0; mt < 2; mt++)
                #pragma unroll
                for (int nt = 0; nt < 8; nt++) {
                    uint32_t b0 = (nt & 1) ? b[nt >> 1][2] : b[nt >> 1][0];
                    uint32_t b1 = (nt & 1) ? b[nt >> 1][3] : b[nt >> 1][1];
                    mma16816(acc[mt][nt], a[mt][0], a[mt][1], a[mt][2], a[mt][3],
                             b0, b1);
                }
        }

        // ---- epilogue: warp-local row maxima, guarded emission ----
        #pragma unroll
        for (int mt = 0; mt < 2; mt++) {
            float ma = -CUDART_INF_F, mb = -CUDART_INF_F;
            #pragma unroll
            for (int nt = 0; nt < 8; nt++) {
                ma = fmaxf(ma, fmaxf(acc[mt][nt][0], acc[mt][nt][1]));
                mb = fmaxf(mb, fmaxf(acc[mt][nt][2], acc[mt][nt][3]));
            }
            ma = fmaxf(ma, __shfl_xor_sync(0xffffffffu, ma, 1));
            ma = fmaxf(ma, __shfl_xor_sync(0xffffffffu, ma, 2));
            mb = fmaxf(mb, __shfl_xor_sync(0xffffffffu, mb, 1));
            mb = fmaxf(mb, __shfl_xor_sync(0xffffffffu, mb, 2));
            const bool anyA = (ma >= thrA[mt] - DELTA_C);
            const bool anyB = (mb >= thrB[mt] - DELTA_C);
            thrA[mt] = fmaxf(thrA[mt], ma);
            thrB[mt] = fmaxf(thrB[mt], mb);
            const int rA = wm * 32 + mt * 16 + qr;
            const int rB = rA + 8;
            if (anyA) {
                const float cutA = thrA[mt] - DELTA_C;
                #pragma unroll
                for (int nt = 0; nt < 8; nt++) {
                    int kb = t * 128 + wn * 64 + nt * 8 + 2 * qc;
                    if (acc[mt][nt][0] >= cutA) {
                        int p = atomicAdd(&scnt[rA], 1);
                        if (p < CAP) g_cand[(size_t)(row0 + rA) * CAP + p] =
                            make_int2(__float_as_int(acc[mt][nt][0]), kb);
                    }
                    if (acc[mt][nt][1] >= cutA) {
                        int p = atomicAdd(&scnt[rA], 1);
                        if (p < CAP) g_cand[(size_t)(row0 + rA) * CAP + p] =
                            make_int2(__float_as_int(acc[mt][nt][1]), kb + 1);
                    }
                }
            }
            if (anyB) {
                const float cutB = thrB[mt] - DELTA_C;
                #pragma unroll
                for (int nt = 0; nt < 8; nt++) {
                    int kb = t * 128 + wn * 64 + nt * 8 + 2 * qc;
                    if (acc[mt][nt][2] >= cutB) {
                        int p = atomicAdd(&scnt[rB], 1);
                        if (p < CAP) g_cand[(size_t)(row0 + rB) * CAP + p] =
                            make_int2(__float_as_int(acc[mt][nt][2]), kb);
                    }
                    if (acc[mt][nt][3] >= cutB) {
                        int p = atomicAdd(&scnt[rB], 1);
                        if (p < CAP) g_cand[(size_t)(row0 + rB) * CAP + p] =
                            make_int2(__float_as_int(acc[mt][nt][3]), kb + 1);
                    }
                }
            }
        }
        __syncthreads();   // buf(t) reads done before next iteration's cp.async
    }

    if (tid < 128) g_ccnt[row0 + tid] = scnt[tid];
}

// ---------------------------------------------------------------------------
// rescore + gather (fused): global-max prune on stored bf16 scores with smem
// SURVIVOR COMPACTION (each lane then runs at most one exact chain), exact
// fp32 chains (arithmetic identical to R1-R11), then straight-through output,
// loss sums and histogram. 16 lanes/row, 2 rows/warp.
// ---------------------------------------------------------------------------
__global__ void __launch_bounds__(256) k_rescore_gather(
    const float* __restrict__ X, const float* __restrict__ E,
    float* __restrict__ out, int out_size)
{
    __shared__ float xs[16][132];
    __shared__ double swe[8], swq[8];
    __shared__ int scnt2[16];
    __shared__ int slist[16][CAP];
    const int warp = threadIdx.x >> 5;
    const int lane = threadIdx.x & 31;
    const int grp  = lane >> 4;     // 0..1: row within warp
    const int l16  = lane & 15;     // lane within 16-lane group
    const int rowL = warp * 2 + grp;
    const int row  = blockIdx.x * 16 + rowL;

    for (int i = threadIdx.x; i < 16 * 32; i += 256) {
        int r = i >> 5, c = i & 31;
        float4 v = ((const float4*)X)[(size_t)(blockIdx.x * 16 + r) * 32 + c];
        *(float4*)&xs[r][c * 4] = v;
    }
    if (threadIdx.x < 16) scnt2[threadIdx.x] = 0;
    __syncthreads();

    const float* xr = xs[rowL];
    // A = |x|^2 in fp64, reduced within the 16-lane group
    double s = 0.0;
    #pragma unroll
    for (int i = 0; i < 8; i++) { double v = (double)xr[l16 * 8 + i]; s += v * v; }
    #pragma unroll
    for (int off = 1; off < 16; off <<= 1)
        s += __shfl_xor_sync(0xffffffffu, s, off);
    float A = (float)s;

    int n = g_ccnt[row];
    float best = CUDART_INF_F;
    int bi = 0x7fffffff;

    if (n <= CAP) {
        const int2* cd = &g_cand[(size_t)row * CAP];
        // pass A: global bf16-score max over this row's candidates
        float vmax = -CUDART_INF_F;
        for (int j = l16; j < n; j += 16)
            vmax = fmaxf(vmax, __int_as_float(cd[j].x));
        #pragma unroll
        for (int off = 1; off < 16; off <<= 1)
            vmax = fmaxf(vmax, __shfl_xor_sync(0xffffffffu, vmax, off));
        const float cut = vmax - DELTA_C;
        // pass A2: compact survivors into smem (few pushes per row)
        for (int j = l16; j < n; j += 16) {
            int2 c = cd[j];
            if (__int_as_float(c.x) >= cut) {
                int p = atomicAdd(&scnt2[rowL], 1);
                slist[rowL][p] = c.y;
            }
        }
        __syncwarp();
        const int m = scnt2[rowL];
        // pass B: one exact fp32 chain per lane (loop only if >16 survivors)
        for (int si = l16; si < m; si += 16) {
            int k = slist[rowL][si];
            const float4* e4 = (const float4*)(E + (size_t)k * D_N);
            float acc = 0.0f;
            #pragma unroll 8
            for (int i = 0; i < 32; i++) {
                float4 xv = *(const float4*)&xr[i * 4];
                float4 ev = e4[i];
                acc = __fmaf_rn(xv.x, ev.x, acc);
                acc = __fmaf_rn(xv.y, ev.y, acc);
                acc = __fmaf_rn(xv.z, ev.z, acc);
                acc = __fmaf_rn(xv.w, ev.w, acc);
            }
            float tsum = __fadd_rn(A, g_esq[k]);
            float v = __fmaf_rn(-2.0f, acc, tsum);
            if (v < best || (v == best && k < bi)) { best = v; bi = k; }
        }
    } else {
        // safety fallback: exact full scan (unreachable in practice)
        for (int k = l16; k < K_N; k += 16) {
            const float4* e4 = (const float4*)(E + (size_t)k * D_N);
            float acc = 0.0f;
            #pragma unroll 8
            for (int i = 0; i < 32; i++) {
                float4 xv = *(const float4*)&xr[i * 4];
                float4 ev = e4[i];
                acc = __fmaf_rn(xv.x, ev.x, acc);
                acc = __fmaf_rn(xv.y, ev.y, acc);
                acc = __fmaf_rn(xv.z, ev.z, acc);
                acc = __fmaf_rn(xv.w, ev.w, acc);
            }
            float tsum = __fadd_rn(A, g_esq[k]);
            float v = __fmaf_rn(-2.0f, acc, tsum);
            if (v < best || (v == best && k < bi)) { best = v; bi = k; }
        }
    }
    // butterfly reduce within 16-lane group -> all lanes hold (best, bi)
    #pragma unroll
    for (int off = 1; off < 16; off <<= 1) {
        float ov = __shfl_xor_sync(0xffffffffu, best, off);
        int   oi = __shfl_xor_sync(0xffffffffu, bi, off);
        if (ov < best || (ov == best && oi < bi)) { best = ov; bi = oi; }
    }

    // ---- gather: straight-through output + loss sums + histogram ----
    const float4* e4 = (const float4*)(E + (size_t)bi * D_N);
    float4 q0 = e4[l16 * 2], q1 = e4[l16 * 2 + 1];
    float4 x0 = *(const float4*)&xr[l16 * 8];
    float4 x1 = *(const float4*)&xr[l16 * 8 + 4];
    float4 o0, o1;
    double se = 0.0, sq = 0.0;
#define VQ_STEP(o, q, x) { \
        float de = __fsub_rn(q, x); float qs = __fadd_rn(x, de); \
        float dq = __fsub_rn(qs, x); \
        o = qs; se += (double)de * (double)de; sq += (double)dq * (double)dq; }
    VQ_STEP(o0.x, q0.x, x0.x)  VQ_STEP(o0.y, q0.y, x0.y)
    VQ_STEP(o0.z, q0.z, x0.z)  VQ_STEP(o0.w, q0.w, x0.w)
    VQ_STEP(o1.x, q1.x, x1.x)  VQ_STEP(o1.y, q1.y, x1.y)
    VQ_STEP(o1.z, q1.z, x1.z)  VQ_STEP(o1.w, q1.w, x1.w)
#undef VQ_STEP
    ((float4*)out)[(size_t)row * 32 + l16 * 2]     = o0;
    ((float4*)out)[(size_t)row * 32 + l16 * 2 + 1] = o1;

    if (l16 == 0) {
        atomicAdd(&g_counts[bi], 1);
        if (out_size >= B_N * D_N + B_N)
            out[(size_t)B_N * D_N + row] = (float)bi;
    }

    // block-reduce loss sums
    #pragma unroll
    for (int off = 16; off > 0; off >>= 1) {
        se += __shfl_down_sync(0xffffffffu, se, off);
        sq += __shfl_down_sync(0xffffffffu, sq, off);
    }
    if (lane == 0) { swe[warp] = se; swq[warp] = sq; }
    __syncthreads();
    if (threadIdx.x == 0) {
        double te = 0.0, tq = 0.0;
        #pragma unroll
        for (int i = 0; i < 8; i++) { te += swe[i]; tq += swq[i]; }
        atomicAdd(&g_sum_e, te);
        atomicAdd(&g_sum_q, tq);
    }
}

// ---------------------------------------------------------------------------
// final: entropy + scalar outputs in one kernel (single CTA, 1024 threads)
// ---------------------------------------------------------------------------
__global__ void k_final(float* __restrict__ out, int out_size) {
    if (out_size < B_N * D_N + B_N + 4) return;
    __shared__ double sh[1024];
    int tid = threadIdx.x;
    double h = 0.0;
    #pragma unroll
    for (int r = 0; r < K_N / 1024; r++) {
        int k = r * 1024 + tid;
        float p = __fmul_rn((float)g_counts[k], 1.0f / 32768.0f);
        float t = __fmul_rn(p, logf(__fadd_rn(p, 1e-10f)));
        h += (double)t;
    }
    sh[tid] = h;
    __syncthreads();
    for (int s = 512; s > 0; s >>= 1) {
        if (tid < s) sh[tid] += sh[tid + s];
        __syncthreads();
    }
    if (tid == 0) {
        float H = (float)sh[0];
        float perp = expf(-H);
        double n = (double)B_N * (double)D_N;
        float e = (float)(g_sum_e / n);
        float q = (float)(g_sum_q / n);
        float vq = __fadd_rn(q, __fmul_rn(0.25f, e));
        float* s4 = out + (size_t)B_N * D_N + B_N;
        s4[0] = vq; s4[1] = e; s4[2] = q; s4[3] = perp;
    }
}

// ---------------------------------------------------------------------------
extern "C" void kernel_launch(void* const* d_in, const int* in_sizes, int n_in,
                              void* d_out, int out_size)
{
    const float* X = (const float*)d_in[0];
    const float* E = (const float*)d_in[1];
    if (n_in >= 2 && in_sizes[0] == K_N * D_N && in_sizes[1] == B_N * D_N) {
        X = (const float*)d_in[1];
        E = (const float*)d_in[0];
    }
    float* out = (float*)d_out;

    static bool attr_set = false;
    if (!attr_set) {
        cudaFuncSetAttribute(k_phase1,
                             cudaFuncAttributeMaxDynamicSharedMemorySize,
                             SM_TOTAL);
        attr_set = true;
    }

    k_init<<<K_N / 8, 256>>>(E);
    k_phase1<<<B_N / 128, 256, SM_TOTAL>>>(X);
    k_rescore_gather<<<B_N / 16, 256>>>(X, E, out, out_size);
    k_final<<<1, 1024>>>(out, out_size);
}